// round 15
// baseline (speedup 1.0000x reference)
#include <cuda_runtime.h>
#include <cstdint>
#include <math.h>

#define Bc   8
#define Nc   1024
#define OBSc 64
#define HIDc 192
#define Hc   3
#define Dc   64
#define BHc  (Bc*Hc)

#define LDA 36
#define LDB 72
#define JSPLIT 2
#define NTILE_H (Nc / 32 / JSPLIT)
#define NPS 68          // row stride: 64 d + 1 scalar + 3 pad
#define SEGL 128
#define NSEG (Nc/SEGL)  // 8

// Scratch (device globals; no allocation allowed)
__device__ float g_Wh[BHc * Nc * Dc];
__device__ float g_x [Bc * Nc * HIDc];
__device__ float g_si[BHc * Nc];
__device__ float g_sj[BHc * Nc];
__device__ uint32_t g_adjbits[Nc * 32];
__device__ float g_part[JSPLIT][BHc * Nc * Dc];
__device__ float g_pden[JSPLIT][BHc * Nc];
__device__ int   g_full;
__device__ unsigned long long g_keys[BHc * Nc];   // packed (sortable(s_j), idx)
__device__ float g_sv[BHc * Nc];
__device__ int   g_perm[BHc * Nc];
__device__ int   g_krank[BHc * Nc];
__device__ float g_smax[BHc];
__device__ float g_PSl1[(size_t)BHc * Nc * NPS];
__device__ float g_PSl2[(size_t)BHc * Nc * NPS];
__device__ float g_segtot1[BHc * NSEG * NPS];
__device__ float g_segtot2[BHc * NSEG * NPS];
__device__ float g_segoff1[BHc * (NSEG + 1) * NPS];
__device__ float g_segoff2[BHc * (NSEG + 1) * NPS];

__device__ __forceinline__ uint32_t tf32u(float x){
    uint32_t u; asm("cvt.rna.tf32.f32 %0, %1;" : "=r"(u) : "f"(x));
    return u;
}
__device__ __forceinline__ uint32_t f2sort(float x){
    uint32_t b = __float_as_uint(x);
    return b ^ (uint32_t)(((int32_t)b >> 31) | 0x80000000);
}
__device__ __forceinline__ void mma8(float* d, uint32_t a0, uint32_t a1, uint32_t a2, uint32_t a3,
                                     uint32_t b0, uint32_t b1){
    asm volatile("mma.sync.aligned.m16n8k8.row.col.f32.tf32.tf32.f32 "
        "{%0,%1,%2,%3}, {%4,%5,%6,%7}, {%8,%9}, {%0,%1,%2,%3};"
        : "+f"(d[0]), "+f"(d[1]), "+f"(d[2]), "+f"(d[3])
        : "r"(a0), "r"(a1), "r"(a2), "r"(a3), "r"(b0), "r"(b1));
}

// ---------------------------------------------------------------------------
__global__ void init_kernel(void){ if (threadIdx.x == 0) g_full = 1; }

__global__ __launch_bounds__(256) void adjbits_kernel(const float* __restrict__ adj)
{
    int w = (blockIdx.x * blockDim.x + threadIdx.x) >> 5;
    int lane = threadIdx.x & 31;
    if (w < Nc * 32){
        float v = adj[(size_t)w * 32 + lane];
        uint32_t m = __ballot_sync(0xffffffffu, v > 0.f);
        if (lane == 0){
            g_adjbits[w] = m;
            if (m != 0xffffffffu) g_full = 0;
        }
    }
}

// ---------------------------------------------------------------------------
// Projection (tf32 mma) with register prefetch of tile t+1.
// ---------------------------------------------------------------------------
template<int K, bool FROM_GX>
__global__ __launch_bounds__(256) void proj_mma(const float* __restrict__ Xe,
                                                const float* __restrict__ W,
                                                const float* __restrict__ av)
{
    __shared__ uint32_t As[128 * LDA];
    __shared__ uint32_t Bs[32 * LDB];
    __shared__ float sa[128];

    int tid = threadIdx.x, lane = tid & 31, wid = tid >> 5;
    int g = lane >> 2, tig = lane & 3, wr0 = wid * 16;
    int row0 = blockIdx.x * 128, h = blockIdx.y;
    const float* X = FROM_GX ? (const float*)g_x : Xe;

    if (tid < 128) sa[tid] = av[h * 128 + tid];

    int ar = tid >> 1, ac = (tid & 1) * 16;
    int bk = tid >> 3, bd = (tid & 7) * 8;

    float4 xa[4], wb[2];
    {
        const float* xp = &X[(size_t)(row0 + ar) * K + ac];
        #pragma unroll
        for (int q = 0; q < 4; q++) xa[q] = *(const float4*)&xp[q * 4];
        const float* wp = &W[(size_t)(h * K + bk) * Dc + bd];
        wb[0] = *(const float4*)&wp[0]; wb[1] = *(const float4*)&wp[4];
    }

    float acc[8][4] = {};
    constexpr int NT = K / 32;

    for (int t = 0; t < NT; t++){
        {
            const float* xf = (const float*)xa;
            #pragma unroll
            for (int e = 0; e < 16; e++) As[ar * LDA + ac + e] = tf32u(xf[e]);
            const float* wf = (const float*)wb;
            #pragma unroll
            for (int e = 0; e < 8; e++) Bs[bk * LDB + bd + e] = tf32u(wf[e]);
        }
        __syncthreads();
        if (t + 1 < NT){
            const float* xp = &X[(size_t)(row0 + ar) * K + (t + 1) * 32 + ac];
            #pragma unroll
            for (int q = 0; q < 4; q++) xa[q] = *(const float4*)&xp[q * 4];
            const float* wp = &W[(size_t)(h * K + (t + 1) * 32 + bk) * Dc + bd];
            wb[0] = *(const float4*)&wp[0]; wb[1] = *(const float4*)&wp[4];
        }
        #pragma unroll
        for (int ks = 0; ks < 4; ks++){
            int ka = ks * 8 + tig;
            uint32_t a0 = As[(wr0 + g    ) * LDA + ka    ];
            uint32_t a1 = As[(wr0 + g + 8) * LDA + ka    ];
            uint32_t a2 = As[(wr0 + g    ) * LDA + ka + 4];
            uint32_t a3 = As[(wr0 + g + 8) * LDA + ka + 4];
            #pragma unroll
            for (int nt = 0; nt < 8; nt++){
                uint32_t b0 = Bs[ ka      * LDB + nt * 8 + g];
                uint32_t b1 = Bs[(ka + 4) * LDB + nt * 8 + g];
                mma8(acc[nt], a0, a1, a2, a3, b0, b1);
            }
        }
        __syncthreads();
    }

    float si0 = 0.f, sj0 = 0.f, si1 = 0.f, sj1 = 0.f;
    #pragma unroll
    for (int nt = 0; nt < 8; nt++){
        #pragma unroll
        for (int c = 0; c < 2; c++){
            int col = nt * 8 + 2 * tig + c;
            float al = sa[col], ar2 = sa[64 + col];
            si0 += acc[nt][c] * al;      sj0 += acc[nt][c] * ar2;
            si1 += acc[nt][2 + c] * al;  sj1 += acc[nt][2 + c] * ar2;
        }
    }
    si0 += __shfl_xor_sync(0xffffffffu, si0, 1); si0 += __shfl_xor_sync(0xffffffffu, si0, 2);
    sj0 += __shfl_xor_sync(0xffffffffu, sj0, 1); sj0 += __shfl_xor_sync(0xffffffffu, sj0, 2);
    si1 += __shfl_xor_sync(0xffffffffu, si1, 1); si1 += __shfl_xor_sync(0xffffffffu, si1, 2);
    sj1 += __shfl_xor_sync(0xffffffffu, sj1, 1); sj1 += __shfl_xor_sync(0xffffffffu, sj1, 2);

    int r = row0 + wr0 + g;
    int b = r >> 10, n = r & (Nc - 1);
    int bh = b * Hc + h;
    if (tig == 0){
        g_si[(size_t)bh * Nc + n] = si0;     g_sj[(size_t)bh * Nc + n] = sj0;
        g_si[(size_t)bh * Nc + n + 8] = si1; g_sj[(size_t)bh * Nc + n + 8] = sj1;
    }
    float* wh0 = &g_Wh[((size_t)bh * Nc + n    ) * Dc];
    float* wh1 = &g_Wh[((size_t)bh * Nc + n + 8) * Dc];
    #pragma unroll
    for (int nt = 0; nt < 8; nt++){
        *(float2*)&wh0[nt * 8 + 2 * tig] =
            make_float2(__uint_as_float(tf32u(acc[nt][0])), __uint_as_float(tf32u(acc[nt][1])));
        *(float2*)&wh1[nt * 8 + 2 * tig] =
            make_float2(__uint_as_float(tf32u(acc[nt][2])), __uint_as_float(tf32u(acc[nt][3])));
    }
}

// ---------------------------------------------------------------------------
// FAST PATH sort stage 1: sort 256-element chunks with packed u64 keys.
// Grid (4, BHc), 256 threads. Warp bitonic + 3 ranking-merge rounds.
// ---------------------------------------------------------------------------
__global__ __launch_bounds__(256) void sort1_kernel(void)
{
    if (!g_full) return;
    __shared__ unsigned long long ka[256], kb[256];
    int chunk = blockIdx.x, bh = blockIdx.y, tid = threadIdx.x, lane = tid & 31;
    int idx = chunk * 256 + tid;

    unsigned long long key =
        ((unsigned long long)f2sort(g_sj[(size_t)bh * Nc + idx]) << 32) | (uint32_t)idx;

    #pragma unroll
    for (int k = 2; k <= 32; k <<= 1){
        #pragma unroll
        for (int j = k >> 1; j > 0; j >>= 1){
            unsigned long long other = __shfl_xor_sync(0xffffffffu, key, j);
            bool keepLarger = (((lane & k) == 0) == ((lane & j) != 0));
            bool gt = key > other;
            if (keepLarger ? !gt : gt) key = other;
        }
    }
    ka[tid] = key;
    __syncthreads();

    unsigned long long *src = ka, *dst = kb;
    #pragma unroll
    for (int L = 32; L < 256; L <<= 1){
        unsigned long long kv = src[tid];
        int base = tid & ~((L << 1) - 1);
        int local = tid - base;
        bool inA = local < L;
        int myPos = inA ? local : local - L;
        int sBase = base + (inA ? L : 0);
        int lo = 0, hi = L;
        while (lo < hi){
            int mid = (lo + hi) >> 1;
            if (src[sBase + mid] < kv) lo = mid + 1; else hi = mid;
        }
        dst[base + myPos + lo] = kv;
        __syncthreads();
        unsigned long long* t2 = src; src = dst; dst = t2;
    }
    g_keys[(size_t)bh * Nc + chunk * 256 + tid] = src[tid];
}

// ---------------------------------------------------------------------------
// FAST PATH sort stage 2: merge four 256-runs -> 1024; emit sv/perm/krank/smax.
// Grid BHc, 1024 threads.
// ---------------------------------------------------------------------------
__global__ __launch_bounds__(1024) void sort2_kernel(void)
{
    if (!g_full) return;
    __shared__ unsigned long long ka[Nc], kb[Nc];
    int bh = blockIdx.x, tid = threadIdx.x;

    ka[tid] = g_keys[(size_t)bh * Nc + tid];
    __syncthreads();

    unsigned long long *src = ka, *dst = kb;
    #pragma unroll
    for (int L = 256; L < Nc; L <<= 1){
        unsigned long long kv = src[tid];
        int base = tid & ~((L << 1) - 1);
        int local = tid - base;
        bool inA = local < L;
        int myPos = inA ? local : local - L;
        int sBase = base + (inA ? L : 0);
        int lo = 0, hi = L;
        while (lo < hi){
            int mid = (lo + hi) >> 1;
            if (src[sBase + mid] < kv) lo = mid + 1; else hi = mid;
        }
        dst[base + myPos + lo] = kv;
        __syncthreads();
        unsigned long long* t2 = src; src = dst; dst = t2;
    }

    unsigned long long key = src[tid];
    uint32_t s = (uint32_t)(key >> 32);
    uint32_t mask = (s & 0x80000000u) ? 0x80000000u : 0xFFFFFFFFu;
    float sv = __uint_as_float(s ^ mask);
    g_sv[(size_t)bh * Nc + tid] = sv;
    g_perm[(size_t)bh * Nc + tid] = (int)(uint32_t)key;

    // krank: #{ s_j <= -s_i }  via packed threshold key
    {
        float t = -g_si[(size_t)bh * Nc + tid];
        unsigned long long thr = ((unsigned long long)f2sort(t) << 32) | 0xFFFFFFFFull;
        int lo = 0, hi = Nc;
        while (lo < hi){
            int mid = (lo + hi) >> 1;
            if (src[mid] <= thr) lo = mid + 1; else hi = mid;
        }
        g_krank[(size_t)bh * Nc + tid] = lo;
    }
    if (tid == Nc - 1) g_smax[bh] = sv;
}

// ---------------------------------------------------------------------------
// FAST PATH: per-segment local exclusive prefix + segment totals.
// ---------------------------------------------------------------------------
__global__ __launch_bounds__(256) void localscan_kernel(void)
{
    if (!g_full) return;
    __shared__ float e1[SEGL], e2[SEGL];
    __shared__ int   sp[SEGL];
    __shared__ float sub1[16][NPS], sub2[16][NPS];

    int s = blockIdx.x, bh = blockIdx.y, tid = threadIdx.x;
    int kbase = s * SEGL;

    if (tid < SEGL){
        float v = g_sv[(size_t)bh * Nc + kbase + tid];
        e1[tid] = expf(v); e2[tid] = expf(0.2f * v);
        sp[tid] = g_perm[(size_t)bh * Nc + kbase + tid];
    }
    __syncthreads();

    int cq = tid & 15, sub = tid >> 4;
    const float* whb = &g_Wh[(size_t)bh * Nc * Dc];

    float4 w[8];
    #pragma unroll
    for (int u = 0; u < 8; u++)
        w[u] = *(const float4*)&whb[(size_t)sp[sub * 8 + u] * Dc + cq * 4];

    float4 a1 = make_float4(0,0,0,0), a2 = a1;
    float sc1 = 0.f, sc2 = 0.f;
    #pragma unroll
    for (int u = 0; u < 8; u++){
        int k = sub * 8 + u;
        float x1 = e1[k], x2 = e2[k];
        a1.x += x1 * w[u].x; a1.y += x1 * w[u].y; a1.z += x1 * w[u].z; a1.w += x1 * w[u].w;
        a2.x += x2 * w[u].x; a2.y += x2 * w[u].y; a2.z += x2 * w[u].z; a2.w += x2 * w[u].w;
        sc1 += x1; sc2 += x2;
    }
    *(float4*)&sub1[sub][cq * 4] = a1;
    *(float4*)&sub2[sub][cq * 4] = a2;
    if (cq == 0){ sub1[sub][64] = sc1; sub2[sub][64] = sc2; }
    __syncthreads();

    if (tid < 65){
        float o1 = 0.f, o2 = 0.f;
        #pragma unroll
        for (int q = 0; q < 16; q++){
            float t1 = sub1[q][tid]; sub1[q][tid] = o1; o1 += t1;
            float t2 = sub2[q][tid]; sub2[q][tid] = o2; o2 += t2;
        }
        g_segtot1[(bh * NSEG + s) * NPS + tid] = o1;
        g_segtot2[(bh * NSEG + s) * NPS + tid] = o2;
    }
    __syncthreads();

    float4 r1 = *(float4*)&sub1[sub][cq * 4];
    float4 r2 = *(float4*)&sub2[sub][cq * 4];
    float rs1 = sub1[sub][64], rs2 = sub2[sub][64];
    float* P1 = &g_PSl1[((size_t)bh * Nc + kbase) * NPS];
    float* P2 = &g_PSl2[((size_t)bh * Nc + kbase) * NPS];
    #pragma unroll
    for (int u = 0; u < 8; u++){
        int k = sub * 8 + u;
        *(float4*)&P1[(size_t)k * NPS + cq * 4] = r1;
        *(float4*)&P2[(size_t)k * NPS + cq * 4] = r2;
        float x1 = e1[k], x2 = e2[k];
        r1.x += x1 * w[u].x; r1.y += x1 * w[u].y; r1.z += x1 * w[u].z; r1.w += x1 * w[u].w;
        r2.x += x2 * w[u].x; r2.y += x2 * w[u].y; r2.z += x2 * w[u].z; r2.w += x2 * w[u].w;
        if (cq == 0){
            P1[(size_t)k * NPS + 64] = rs1;
            P2[(size_t)k * NPS + 64] = rs2;
            rs1 += x1; rs2 += x2;
        }
    }
}

// ---------------------------------------------------------------------------
// FAST PATH: scan segment totals -> offsets (row NSEG = grand total).
// ---------------------------------------------------------------------------
__global__ __launch_bounds__(96) void scanoff_kernel(void)
{
    if (!g_full) return;
    int bh = blockIdx.x, c = threadIdx.x;
    if (c >= 65) return;
    float o1 = 0.f, o2 = 0.f;
    #pragma unroll
    for (int s = 0; s < NSEG; s++){
        g_segoff1[(bh * (NSEG + 1) + s) * NPS + c] = o1;
        g_segoff2[(bh * (NSEG + 1) + s) * NPS + c] = o2;
        o1 += g_segtot1[(bh * NSEG + s) * NPS + c];
        o2 += g_segtot2[(bh * NSEG + s) * NPS + c];
    }
    g_segoff1[(bh * (NSEG + 1) + NSEG) * NPS + c] = o1;
    g_segoff2[(bh * (NSEG + 1) + NSEG) * NPS + c] = o2;
}

// ---------------------------------------------------------------------------
// OUTPUT (merged fast+fallback): one warp per row; branch on g_full.
// ---------------------------------------------------------------------------
template<bool ELU, bool TO_GX>
__global__ __launch_bounds__(256) void output_kernel(float* __restrict__ out_ext)
{
    int lane = threadIdx.x & 31, wid = threadIdx.x >> 5;
    int row = blockIdx.x * 8 + wid;
    int bh = row >> 10, n = row & (Nc - 1);
    int b = bh / Hc, hh = bh % Hc;
    float* op = (TO_GX ? (float*)g_x : out_ext) + (size_t)(b * Nc + n) * HIDc + hh * Dc;

    float v0, v1;
    if (g_full){
        float s_i = g_si[row];
        float smax = g_smax[bh];
        float e = s_i + smax;
        float m = e > 0.f ? e : 0.2f * e;
        float pa1 = expf(s_i - m), pa2 = expf(0.2f * s_i - m);
        int k = g_krank[row];
        int s = k >> 7;

        const float* SO1 = &g_segoff1[(bh * (NSEG + 1) + s) * NPS];
        const float* SO2 = &g_segoff2[(bh * (NSEG + 1) + s) * NPS];
        const float* T1  = &g_segoff1[(bh * (NSEG + 1) + NSEG) * NPS];

        float2 so1 = *(const float2*)&SO1[lane * 2];
        float2 so2 = *(const float2*)&SO2[lane * 2];
        float2 t1  = *(const float2*)&T1[lane * 2];
        float so1s = SO1[64], so2s = SO2[64], t1s = T1[64];

        float2 pl1 = make_float2(0.f, 0.f), pl2 = pl1;
        float pl1s = 0.f, pl2s = 0.f;
        if (k < Nc){
            const float* P1 = &g_PSl1[((size_t)bh * Nc + k) * NPS];
            const float* P2 = &g_PSl2[((size_t)bh * Nc + k) * NPS];
            pl1 = *(const float2*)&P1[lane * 2];
            pl2 = *(const float2*)&P2[lane * 2];
            pl1s = P1[64]; pl2s = P2[64];
        }
        float den = pa1 * (t1s - (so1s + pl1s)) + pa2 * (so2s + pl2s);
        float inv = 1.f / den;
        v0 = (pa1 * (t1.x - (so1.x + pl1.x)) + pa2 * (so2.x + pl2.x)) * inv;
        v1 = (pa1 * (t1.y - (so1.y + pl1.y)) + pa2 * (so2.y + pl2.y)) * inv;
    } else {
        float inv = 1.f / (g_pden[0][row] + g_pden[1][row]);
        float2 u0 = *(const float2*)&g_part[0][(size_t)row * Dc + lane * 2];
        float2 u1 = *(const float2*)&g_part[1][(size_t)row * Dc + lane * 2];
        v0 = (u0.x + u1.x) * inv;
        v1 = (u0.y + u1.y) * inv;
    }
    if (ELU){
        v0 = v0 > 0.f ? v0 : expm1f(v0);
        v1 = v1 > 0.f ? v1 : expm1f(v1);
    }
    *(float2*)&op[lane * 2] = make_float2(v0, v1);
}

// ---------------------------------------------------------------------------
// FALLBACK (general adjacency): j-split attention partials.
// ---------------------------------------------------------------------------
__global__ __launch_bounds__(256) void attn_frag(void)
{
    if (g_full) return;
    __shared__ __align__(16) float4 jtab[Nc / JSPLIT];
    __shared__ float sil[128], A1v[128], A2v[128], red[8];
    __shared__ __align__(16) uint32_t wsf[2][32 * 64];

    int tid = threadIdx.x, lane = tid & 31, wid = tid >> 5;
    int g = lane >> 2, tig = lane & 3, wr0 = wid * 16;
    int r0 = wr0 + g, r1 = r0 + 8;
    int bh = blockIdx.y, i0 = blockIdx.x * 128;
    int jh = blockIdx.z, jbase = jh * (Nc / JSPLIT);

    const float* sjg = &g_sj[(size_t)bh * Nc];
    const float* sig = &g_si[(size_t)bh * Nc];

    float lmax = -3.0e38f;
    for (int j = tid; j < Nc; j += 256) lmax = fmaxf(lmax, sjg[j]);
    #pragma unroll
    for (int o = 16; o; o >>= 1) lmax = fmaxf(lmax, __shfl_xor_sync(0xffffffffu, lmax, o));
    if (lane == 0) red[wid] = lmax;
    __syncthreads();
    float smax = red[0];
    #pragma unroll
    for (int w2 = 1; w2 < 8; w2++) smax = fmaxf(smax, red[w2]);
    for (int j = tid; j < Nc / JSPLIT; j += 256){
        float v = sjg[jbase + j];
        jtab[j].x = v; jtab[j].y = expf(v); jtab[j].z = expf(0.2f * v);
    }
    if (tid < 128){
        float s = sig[i0 + tid]; sil[tid] = s;
        float e = s + smax; float m = e > 0.f ? e : 0.2f * e;
        A1v[tid] = expf(s - m); A2v[tid] = expf(0.2f * s - m);
    }
    __syncthreads();

    float psil0 = sil[r0], pa10 = A1v[r0], pa20 = A2v[r0];
    float psil1 = sil[r1], pa11 = A1v[r1], pa21 = A2v[r1];
    const uint32_t* bits0 = &g_adjbits[(size_t)(i0 + r0) * 32 + jh * NTILE_H];
    const uint32_t* bits1 = &g_adjbits[(size_t)(i0 + r1) * 32 + jh * NTILE_H];

    int sk = tid >> 3, snt = tid & 7;
    const float* wsrc = &g_Wh[((size_t)bh * Nc + jbase + sk) * Dc + snt * 8];
    int slot_w0 = (sk & 3) << 1;

    float acc[8][4] = {};
    float d0 = 0.f, d1 = 0.f;

    float4 vaN, vbN;
    {
        float4 va = *(const float4*)&wsrc[0];
        float4 vb = *(const float4*)&wsrc[4];
        float v[8] = {va.x, va.y, va.z, va.w, vb.x, vb.y, vb.z, vb.w};
        #pragma unroll
        for (int gc = 0; gc < 8; gc++)
            wsf[0][sk * 64 + ((gc ^ slot_w0) << 3) + snt] = __float_as_uint(v[gc]);
    }
    vaN = *(const float4*)&wsrc[(size_t)32 * Dc];
    vbN = *(const float4*)&wsrc[(size_t)32 * Dc + 4];
    uint32_t wA_c = bits0[0], wB_c = bits1[0];
    uint32_t wA_n = bits0[1], wB_n = bits1[1];
    __syncthreads();

    for (int t = 0; t < NTILE_H; t++){
        float4 va2 = make_float4(0,0,0,0), vb2 = va2;
        uint32_t wA2 = 0, wB2 = 0;
        if (t + 2 < NTILE_H){
            va2 = *(const float4*)&wsrc[(size_t)(t + 2) * 32 * Dc];
            vb2 = *(const float4*)&wsrc[(size_t)(t + 2) * 32 * Dc + 4];
            wA2 = bits0[t + 2]; wB2 = bits1[t + 2];
        }
        if (t + 1 < NTILE_H){
            float v[8] = {vaN.x, vaN.y, vaN.z, vaN.w, vbN.x, vbN.y, vbN.z, vbN.w};
            uint32_t* W = wsf[(t + 1) & 1];
            #pragma unroll
            for (int gc = 0; gc < 8; gc++)
                W[sk * 64 + ((gc ^ slot_w0) << 3) + snt] = __float_as_uint(v[gc]);
        }
        const uint32_t* W = wsf[t & 1];
        int slot_r = g ^ (tig << 1);
        #pragma unroll
        for (int ks = 0; ks < 4; ks++){
            int jb = t * 32 + ks * 8;
            float4 t0 = jtab[jb + tig];
            float4 t1 = jtab[jb + tig + 4];
            int sh = ks * 8 + tig;
            float p0 = (psil0 + t0.x > 0.f) ? pa10 * t0.y : pa20 * t0.z; if (!((wA_c >> sh) & 1))       p0 = 0.f;
            float p1 = (psil1 + t0.x > 0.f) ? pa11 * t0.y : pa21 * t0.z; if (!((wB_c >> sh) & 1))       p1 = 0.f;
            float p2 = (psil0 + t1.x > 0.f) ? pa10 * t1.y : pa20 * t1.z; if (!((wA_c >> (sh + 4)) & 1)) p2 = 0.f;
            float p3 = (psil1 + t1.x > 0.f) ? pa11 * t1.y : pa21 * t1.z; if (!((wB_c >> (sh + 4)) & 1)) p3 = 0.f;
            uint32_t a0 = tf32u(p0), a1 = tf32u(p1), a2 = tf32u(p2), a3 = tf32u(p3);
            d0 += __uint_as_float(a0) + __uint_as_float(a2);
            d1 += __uint_as_float(a1) + __uint_as_float(a3);
            const uint32_t* br0 = &W[ sh      * 64 + slot_r * 8];
            const uint32_t* br1 = &W[(sh + 4) * 64 + slot_r * 8];
            uint4 b00 = *(const uint4*)br0;
            uint4 b01 = *(const uint4*)(br0 + 4);
            uint4 b10 = *(const uint4*)br1;
            uint4 b11 = *(const uint4*)(br1 + 4);
            mma8(acc[0], a0, a1, a2, a3, b00.x, b10.x);
            mma8(acc[1], a0, a1, a2, a3, b00.y, b10.y);
            mma8(acc[2], a0, a1, a2, a3, b00.z, b10.z);
            mma8(acc[3], a0, a1, a2, a3, b00.w, b10.w);
            mma8(acc[4], a0, a1, a2, a3, b01.x, b11.x);
            mma8(acc[5], a0, a1, a2, a3, b01.y, b11.y);
            mma8(acc[6], a0, a1, a2, a3, b01.z, b11.z);
            mma8(acc[7], a0, a1, a2, a3, b01.w, b11.w);
        }
        vaN = va2; vbN = vb2;
        wA_c = wA_n; wB_c = wB_n; wA_n = wA2; wB_n = wB2;
        __syncthreads();
    }

    d0 += __shfl_xor_sync(0xffffffffu, d0, 1); d0 += __shfl_xor_sync(0xffffffffu, d0, 2);
    d1 += __shfl_xor_sync(0xffffffffu, d1, 1); d1 += __shfl_xor_sync(0xffffffffu, d1, 2);

    int n = i0 + r0;
    if (tig == 0){
        g_pden[jh][(size_t)bh * Nc + n]     = d0;
        g_pden[jh][(size_t)bh * Nc + n + 8] = d1;
    }
    float* p0o = &g_part[jh][((size_t)bh * Nc + n    ) * Dc];
    float* p1o = &g_part[jh][((size_t)bh * Nc + n + 8) * Dc];
    #pragma unroll
    for (int nt = 0; nt < 8; nt++){
        *(float2*)&p0o[nt * 8 + 2 * tig] = make_float2(acc[nt][0], acc[nt][1]);
        *(float2*)&p1o[nt * 8 + 2 * tig] = make_float2(acc[nt][2], acc[nt][3]);
    }
}

// ---------------------------------------------------------------------------
extern "C" void kernel_launch(void* const* d_in, const int* in_sizes, int n_in,
                              void* d_out, int out_size)
{
    const float* h   = (const float*)d_in[0];
    const float* adj = (const float*)d_in[1];
    const float* W1  = (const float*)d_in[2];
    const float* a1  = (const float*)d_in[3];
    const float* W2  = (const float*)d_in[4];
    const float* a2  = (const float*)d_in[5];
    float* out = (float*)d_out;

    dim3 projGrid(Bc * Nc / 128, Hc);        // (64, 3)
    dim3 sort1Grid(Nc / 256, BHc);           // (4, 24)
    dim3 scanGrid(NSEG, BHc);                // (8, 24)
    dim3 attnGrid(Nc / 128, BHc, JSPLIT);    // fallback
    int rowBlocks = BHc * Nc / 8;            // 3072

    init_kernel<<<1, 32>>>();
    adjbits_kernel<<<(Nc * 32 * 32) / 256, 256>>>(adj);

    // Layer 1
    proj_mma<OBSc, false><<<projGrid, 256>>>(h, W1, a1);
    sort1_kernel<<<sort1Grid, 256>>>();
    sort2_kernel<<<BHc, 1024>>>();
    localscan_kernel<<<scanGrid, 256>>>();
    scanoff_kernel<<<BHc, 96>>>();
    attn_frag<<<attnGrid, 256>>>();                      // no-op when full
    output_kernel<true, true><<<rowBlocks, 256>>>(nullptr);

    // Layer 2
    proj_mma<HIDc, true ><<<projGrid, 256>>>(nullptr, W2, a2);
    sort1_kernel<<<sort1Grid, 256>>>();
    sort2_kernel<<<BHc, 1024>>>();
    localscan_kernel<<<scanGrid, 256>>>();
    scanoff_kernel<<<BHc, 96>>>();
    attn_frag<<<attnGrid, 256>>>();                      // no-op when full
    output_kernel<false, false><<<rowBlocks, 256>>>(out);
}